// round 1
// baseline (speedup 1.0000x reference)
#include <cuda_runtime.h>

#define BSZ 64
#define HID 300
#define SEQ 64
#define VOC 100000
#define G3  900
#define KT  20
#define VT  128

// ---------------- scratch (device globals; no allocation allowed) ----------------
__device__ float g_h[BSZ * HID];
__device__ float g_gi[BSZ * G3];
__device__ float g_gh[BSZ * G3];
__device__ int   g_ids[BSZ];
__device__ unsigned long long g_best[BSZ];

// ---------------- helpers ----------------
__device__ __forceinline__ unsigned ordf(float f) {
    unsigned u = __float_as_uint(f);
    return (u & 0x80000000u) ? ~u : (u | 0x80000000u);
}

__device__ __forceinline__ unsigned long long pack2(float lo, float hi) {
    unsigned long long r;
    asm("mov.b64 %0, {%1,%2};" : "=l"(r) : "f"(lo), "f"(hi));
    return r;
}
__device__ __forceinline__ void unpack2(unsigned long long v, float& lo, float& hi) {
    asm("mov.b64 {%0,%1}, %2;" : "=f"(lo), "=f"(hi) : "l"(v));
}
// packed fp32x2 FMA: d = a*b + c  (ptxas never emits FFMA2 from C++, PTX only)
__device__ __forceinline__ unsigned long long ffma2(unsigned long long a,
                                                    unsigned long long b,
                                                    unsigned long long c) {
    unsigned long long d;
    asm("fma.rn.f32x2 %0, %1, %2, %3;" : "=l"(d) : "l"(a), "l"(b), "l"(c));
    return d;
}

// ---------------- init ----------------
__global__ void k_init() {
    int i = blockIdx.x * blockDim.x + threadIdx.x;
    if (i < BSZ * HID) g_h[i] = 0.0f;
    if (i < BSZ) { g_ids[i] = 0; g_best[i] = 0ULL; }
}

// ---------------- gate GEMMs: gi = x @ W_ih^T + b_ih ; gh = h @ W_hh^T + b_hh ----
// blockIdx.x: j tile (64 wide, 15 tiles over 900), blockIdx.y: gate (0=input,1=hidden)
// 256 threads, thread tile 4b x 4j, f32x2 packed over b-pairs.
__global__ void k_gates(const int* __restrict__ input, const float* __restrict__ emb,
                        const float* __restrict__ W_ih, const float* __restrict__ W_hh,
                        const float* __restrict__ b_ih, const float* __restrict__ b_hh,
                        int step, int decoder) {
    __shared__ float a_s[KT][BSZ + 4];
    __shared__ float w_s[KT][64 + 4];
    __shared__ int   sid[BSZ];

    const int tid  = threadIdx.x;
    const int gate = blockIdx.y;
    const int j0   = blockIdx.x * 64;
    const float* W    = gate ? W_hh : W_ih;
    const float* bias = gate ? b_hh : b_ih;

    if (gate == 0) {
        if (tid < BSZ) sid[tid] = decoder ? g_ids[tid] : input[step * BSZ + tid];
    }
    __syncthreads();

    const int tx = tid & 15;   // j group (x4)
    const int ty = tid >> 4;   // b group (x4)

    unsigned long long acc[2][4];
#pragma unroll
    for (int p = 0; p < 2; p++)
#pragma unroll
        for (int j = 0; j < 4; j++) acc[p][j] = 0ULL;

    for (int k0 = 0; k0 < HID; k0 += KT) {
        for (int idx = tid; idx < BSZ * KT; idx += 256) {
            int b = idx / KT, k = idx % KT;
            float v;
            if (gate) {
                v = g_h[b * HID + k0 + k];
            } else {
                v = emb[(long)sid[b] * HID + k0 + k];
                if (decoder) v = fmaxf(v, 0.0f);
            }
            a_s[k][b] = v;
        }
        for (int idx = tid; idx < 64 * KT; idx += 256) {
            int j = idx / KT, k = idx % KT;
            int jg = j0 + j;
            w_s[k][j] = (jg < G3) ? W[(long)jg * HID + k0 + k] : 0.0f;
        }
        __syncthreads();
#pragma unroll
        for (int k = 0; k < KT; k++) {
            float4 av = *(const float4*)&a_s[k][ty * 4];
            float4 wv = *(const float4*)&w_s[k][tx * 4];
            unsigned long long a01 = pack2(av.x, av.y);
            unsigned long long a23 = pack2(av.z, av.w);
            float wj[4] = {wv.x, wv.y, wv.z, wv.w};
#pragma unroll
            for (int j = 0; j < 4; j++) {
                unsigned long long wd = pack2(wj[j], wj[j]);
                acc[0][j] = ffma2(a01, wd, acc[0][j]);
                acc[1][j] = ffma2(a23, wd, acc[1][j]);
            }
        }
        __syncthreads();
    }

    float* out = gate ? g_gh : g_gi;
#pragma unroll
    for (int j = 0; j < 4; j++) {
        int jg = j0 + tx * 4 + j;
        if (jg >= G3) continue;
        float bi = bias[jg];
#pragma unroll
        for (int p = 0; p < 2; p++) {
            float lo, hi;
            unpack2(acc[p][j], lo, hi);
            int b = ty * 4 + p * 2;
            out[b * G3 + jg]       = lo + bi;
            out[(b + 1) * G3 + jg] = hi + bi;
        }
    }
}

// ---------------- GRU elementwise combine + per-step best reset ----------------
__global__ void k_combine() {
    int idx = blockIdx.x * blockDim.x + threadIdx.x;
    if (idx < BSZ) g_best[idx] = 0ULL;
    if (idx >= BSZ * HID) return;
    int b = idx / HID, i = idx % HID;
    const float* gi = &g_gi[b * G3];
    const float* gh = &g_gh[b * G3];
    float r = 1.0f / (1.0f + expf(-(gi[i] + gh[i])));
    float z = 1.0f / (1.0f + expf(-(gi[HID + i] + gh[HID + i])));
    float n = tanhf(gi[2 * HID + i] + r * gh[2 * HID + i]);
    g_h[idx] = (1.0f - z) * n + z * g_h[idx];
}

// ---------------- fused logits GEMM + bias + argmax ----------------
// Block: 256 threads, tile 64b x 128v; thread tile 8b x 4v (f32x2 over b-pairs).
// argmax key: (ordered_float(logit) << 32) | (0xFFFFFFFF - v)  -> atomicMax gives
// max logit with first-index (lowest v) tie-break, matching jnp.argmax.
__global__ void k_logits(const float* __restrict__ outW, const float* __restrict__ outb) {
    __shared__ float h_s[KT][BSZ + 4];
    __shared__ float w_s[KT][VT + 4];

    const int tid = threadIdx.x;
    const int tx  = tid & 31;   // v group (x4)
    const int ty  = tid >> 5;   // b group (x8), uniform per warp
    const int v0  = blockIdx.x * VT;

    unsigned long long acc[4][4];
#pragma unroll
    for (int p = 0; p < 4; p++)
#pragma unroll
        for (int j = 0; j < 4; j++) acc[p][j] = 0ULL;

    for (int k0 = 0; k0 < HID; k0 += KT) {
        for (int idx = tid; idx < BSZ * KT; idx += 256) {
            int b = idx / KT, k = idx % KT;
            h_s[k][b] = g_h[b * HID + k0 + k];
        }
        for (int idx = tid; idx < VT * KT; idx += 256) {
            int v = idx / KT, k = idx % KT;
            int vg = v0 + v;
            w_s[k][v] = (vg < VOC) ? outW[(long)vg * HID + k0 + k] : 0.0f;
        }
        __syncthreads();
#pragma unroll
        for (int k = 0; k < KT; k++) {
            float4 h0 = *(const float4*)&h_s[k][ty * 8];
            float4 h1 = *(const float4*)&h_s[k][ty * 8 + 4];
            float4 wv = *(const float4*)&w_s[k][tx * 4];
            unsigned long long hp[4] = {pack2(h0.x, h0.y), pack2(h0.z, h0.w),
                                        pack2(h1.x, h1.y), pack2(h1.z, h1.w)};
            float wj[4] = {wv.x, wv.y, wv.z, wv.w};
#pragma unroll
            for (int j = 0; j < 4; j++) {
                unsigned long long wd = pack2(wj[j], wj[j]);
#pragma unroll
                for (int p = 0; p < 4; p++) acc[p][j] = ffma2(hp[p], wd, acc[p][j]);
            }
        }
        __syncthreads();
    }

    unsigned long long best[8];
#pragma unroll
    for (int i = 0; i < 8; i++) best[i] = 0ULL;

#pragma unroll
    for (int j = 0; j < 4; j++) {
        int v = v0 + tx * 4 + j;
        if (v >= VOC) continue;
        float bb = outb[v];
        unsigned lowbits = 0xFFFFFFFFu - (unsigned)v;
#pragma unroll
        for (int p = 0; p < 4; p++) {
            float lo, hi;
            unpack2(acc[p][j], lo, hi);
            lo += bb; hi += bb;
            unsigned long long klo = ((unsigned long long)ordf(lo) << 32) | lowbits;
            unsigned long long khi = ((unsigned long long)ordf(hi) << 32) | lowbits;
            if (klo > best[2 * p])     best[2 * p]     = klo;
            if (khi > best[2 * p + 1]) best[2 * p + 1] = khi;
        }
    }
    // warp reduce over tx (whole warp shares the same 8 b's)
#pragma unroll
    for (int off = 16; off > 0; off >>= 1) {
#pragma unroll
        for (int i = 0; i < 8; i++) {
            unsigned long long o = __shfl_down_sync(0xFFFFFFFFu, best[i], off);
            if (o > best[i]) best[i] = o;
        }
    }
    if (tx == 0) {
#pragma unroll
        for (int i = 0; i < 8; i++) atomicMax(&g_best[ty * 8 + i], best[i]);
    }
}

// ---------------- finalize: decode key -> id, write output ----------------
__global__ void k_finalize(float* __restrict__ out, int step) {
    int b = threadIdx.x;
    if (b < BSZ) {
        unsigned long long key = g_best[b];
        int v = (int)(0xFFFFFFFFu - (unsigned)(key & 0xFFFFFFFFu));
        g_ids[b] = v;
        out[step * BSZ + b] = (float)v;
    }
}

// ---------------- launch ----------------
extern "C" void kernel_launch(void* const* d_in, const int* in_sizes, int n_in,
                              void* d_out, int out_size) {
    const int*   input = (const int*)d_in[0];
    const float* emb   = (const float*)d_in[1];
    const float* eWih  = (const float*)d_in[2];
    const float* eWhh  = (const float*)d_in[3];
    const float* ebih  = (const float*)d_in[4];
    const float* ebhh  = (const float*)d_in[5];
    const float* dWih  = (const float*)d_in[6];
    const float* dWhh  = (const float*)d_in[7];
    const float* dbih  = (const float*)d_in[8];
    const float* dbhh  = (const float*)d_in[9];
    const float* outW  = (const float*)d_in[10];
    const float* outb  = (const float*)d_in[11];
    float* out = (float*)d_out;

    k_init<<<76, 256>>>();

    // encoder
    for (int t = 0; t < SEQ; t++) {
        k_gates<<<dim3(15, 2), 256>>>(input, emb, eWih, eWhh, ebih, ebhh, t, 0);
        k_combine<<<75, 256>>>();
    }
    // decoder (greedy)
    for (int t = 0; t < SEQ; t++) {
        k_gates<<<dim3(15, 2), 256>>>(input, emb, dWih, dWhh, dbih, dbhh, t, 1);
        k_combine<<<75, 256>>>();
        k_logits<<<(VOC + VT - 1) / VT, 256>>>(outW, outb);
        k_finalize<<<1, 64>>>(out, t);
    }
}

// round 2
// speedup vs baseline: 1.5100x; 1.5100x over previous
#include <cuda_runtime.h>

#define BSZ 64
#define HID 300
#define SEQ 64
#define VOC 100000
#define VT  128
#define NBL ((VOC + VT - 1) / VT)   // 782
#define KC  60

typedef unsigned long long ull;

// ---------------- scratch (device globals) ----------------
__device__ float2 g_hp[2][HID * 32];            // packed h, double buffered
__device__ float2 g_egi[SEQ * 900 * 32];        // precomputed encoder input gates (+bias)
__device__ int    g_ids[BSZ];
__device__ ull    g_part[BSZ * NBL];

// ---------------- helpers ----------------
__device__ __forceinline__ unsigned ordf(float f) {
    unsigned u = __float_as_uint(f);
    return (u & 0x80000000u) ? ~u : (u | 0x80000000u);
}
__device__ __forceinline__ void unpack2(ull v, float& lo, float& hi) {
    asm("mov.b64 {%0,%1}, %2;" : "=f"(lo), "=f"(hi) : "l"(v));
}
__device__ __forceinline__ ull ffma2(ull a, ull b, ull c) {
    ull d;
    asm("fma.rn.f32x2 %0, %1, %2, %3;" : "=l"(d) : "l"(a), "l"(b), "l"(c));
    return d;
}

// ---------------- init ----------------
__global__ void k_init() {
    int i = blockIdx.x * blockDim.x + threadIdx.x;
    if (i < HID * 32) g_hp[0][i] = make_float2(0.f, 0.f);
    if (i < BSZ) g_ids[i] = 0;
}

// ---------------- encoder input-gate pre-GEMM (all 64 steps, one launch) -------
// grid (15, 64): j-tile 64 x t. threads 256: tx(16)->4j, ty(16)->2bp.
#define SM_ENCPRE (16320 + 31680 + 256)
__global__ void k_encpre(const int* __restrict__ input, const float* __restrict__ emb,
                         const float* __restrict__ W, const float* __restrict__ bias) {
    extern __shared__ char sm[];
    float2* x_s = (float2*)sm;               // [KC][34]
    float2* w_s = (float2*)(sm + 16320);     // [KC][66] duplicated
    int* sid    = (int*)(sm + 16320 + 31680);
    const int tid = threadIdx.x;
    const int t = blockIdx.y, j0 = blockIdx.x * 64;
    if (tid < BSZ) sid[tid] = input[t * BSZ + tid];
    __syncthreads();
    const int tx = tid & 15, ty = tid >> 4;
    ull acc[2][4] = {};
    for (int k0 = 0; k0 < HID; k0 += KC) {
        for (int idx = tid; idx < 32 * KC; idx += 256) {
            int k = idx >> 5, bp = idx & 31;
            float e0 = emb[(long)sid[2 * bp] * HID + k0 + k];
            float e1 = emb[(long)sid[2 * bp + 1] * HID + k0 + k];
            x_s[k * 34 + bp] = make_float2(e0, e1);
        }
        for (int idx = tid; idx < 64 * 15; idx += 256) {
            int j = idx / 15, q = idx % 15;
            int jg = j0 + j;
            float4 w = (jg < 900) ? *(const float4*)&W[(long)jg * HID + k0 + q * 4]
                                  : make_float4(0, 0, 0, 0);
            w_s[(q * 4 + 0) * 66 + j] = make_float2(w.x, w.x);
            w_s[(q * 4 + 1) * 66 + j] = make_float2(w.y, w.y);
            w_s[(q * 4 + 2) * 66 + j] = make_float2(w.z, w.z);
            w_s[(q * 4 + 3) * 66 + j] = make_float2(w.w, w.w);
        }
        __syncthreads();
#pragma unroll 4
        for (int k = 0; k < KC; k++) {
            ull xp0 = *(const ull*)&x_s[k * 34 + ty];
            ull xp1 = *(const ull*)&x_s[k * 34 + ty + 16];
            ulonglong2 wA = *(const ulonglong2*)&w_s[k * 66 + tx * 4];
            ulonglong2 wB = *(const ulonglong2*)&w_s[k * 66 + tx * 4 + 2];
            acc[0][0] = ffma2(xp0, wA.x, acc[0][0]);
            acc[1][0] = ffma2(xp1, wA.x, acc[1][0]);
            acc[0][1] = ffma2(xp0, wA.y, acc[0][1]);
            acc[1][1] = ffma2(xp1, wA.y, acc[1][1]);
            acc[0][2] = ffma2(xp0, wB.x, acc[0][2]);
            acc[1][2] = ffma2(xp1, wB.x, acc[1][2]);
            acc[0][3] = ffma2(xp0, wB.y, acc[0][3]);
            acc[1][3] = ffma2(xp1, wB.y, acc[1][3]);
        }
        __syncthreads();
    }
#pragma unroll
    for (int jj = 0; jj < 4; jj++) {
        int j = j0 + tx * 4 + jj;
        if (j >= 900) continue;
        float bb = bias[j];
#pragma unroll
        for (int p = 0; p < 2; p++) {
            int bp = ty + 16 * p;
            float a, b; unpack2(acc[p][jj], a, b);
            g_egi[((long)t * 900 + j) * 32 + bp] = make_float2(a + bb, b + bb);
        }
    }
}

// ---------------- fused GRU step (gates + combine) ----------------
// grid 30 (i-tile 10), threads 160: ti = tid/16 (0..9), tb = tid%16 (bp = tb, tb+16)
#define SM_STEP (16320 + 16320 + 28800 + 256)
template <int DEC>
__global__ void k_step(const float* __restrict__ emb,
                       const float* __restrict__ Wih, const float* __restrict__ Whh,
                       const float* __restrict__ bih, const float* __restrict__ bhh,
                       int t, int cur) {
    extern __shared__ char sm[];
    float2* h_s = (float2*)sm;                       // [KC][34]
    float2* x_s = (float2*)(sm + 16320);             // [KC][34]
    float2* w_s = (float2*)(sm + 32640);             // [KC][10][G] duplicated
    int* sid    = (int*)(sm + 32640 + 28800);
    const int G = DEC ? 6 : 3;
    const int tid = threadIdx.x;
    const int ti = tid >> 4, tb = tid & 15;
    const int i0 = blockIdx.x * 10;
    const float2* hp_cur = g_hp[cur];
    float2*       hp_nxt = g_hp[cur ^ 1];
    if (DEC && tid < BSZ) sid[tid] = g_ids[tid];
    __syncthreads();
    ull acc[2][6] = {};
    for (int k0 = 0; k0 < HID; k0 += KC) {
        for (int idx = tid; idx < 32 * KC; idx += 160) {
            int k = idx >> 5, bp = idx & 31;
            h_s[k * 34 + bp] = hp_cur[(k0 + k) * 32 + bp];
            if (DEC) {
                float e0 = fmaxf(emb[(long)sid[2 * bp] * HID + k0 + k], 0.f);
                float e1 = fmaxf(emb[(long)sid[2 * bp + 1] * HID + k0 + k], 0.f);
                x_s[k * 34 + bp] = make_float2(e0, e1);
            }
        }
        const int wcnt = KC * 10 * G;
        for (int idx = tid; idx < wcnt; idx += 160) {
            int ig = idx / KC, k = idx % KC;
            int i, g, gidx;
            if (DEC) { i = ig / 6; g = ig % 6; gidx = g; }
            else     { i = ig / 3; g = 3 + ig % 3; gidx = g - 3; }
            const float* W = (g < 3) ? Wih : Whh;
            int row = (g % 3) * HID + i0 + i;
            float v = W[(long)row * HID + k0 + k];
            w_s[(k * 10 + i) * G + gidx] = make_float2(v, v);
        }
        __syncthreads();
#pragma unroll 4
        for (int k = 0; k < KC; k++) {
            ull hp0 = *(const ull*)&h_s[k * 34 + tb];
            ull hp1 = *(const ull*)&h_s[k * 34 + tb + 16];
            ull xp0 = 0, xp1 = 0;
            if (DEC) {
                xp0 = *(const ull*)&x_s[k * 34 + tb];
                xp1 = *(const ull*)&x_s[k * 34 + tb + 16];
            }
            const float2* wrow = &w_s[(k * 10 + ti) * G];
#pragma unroll
            for (int g = 0; g < G; g++) {
                ull wd = *(const ull*)&wrow[g];
                ull s0 = (DEC && g < 3) ? xp0 : hp0;
                ull s1 = (DEC && g < 3) ? xp1 : hp1;
                acc[0][g] = ffma2(s0, wd, acc[0][g]);
                acc[1][g] = ffma2(s1, wd, acc[1][g]);
            }
        }
        __syncthreads();
    }
    // ---- combine ----
    const int i = i0 + ti;
    const int HH0 = DEC ? 3 : 0;
    float bhr = bhh[i], bhz = bhh[HID + i], bhn = bhh[2 * HID + i];
    float bir = 0, biz = 0, bin = 0;
    if (DEC) { bir = bih[i]; biz = bih[HID + i]; bin = bih[2 * HID + i]; }
#pragma unroll
    for (int p = 0; p < 2; p++) {
        int bp = tb + 16 * p;
        float gr0, gr1, gz0, gz1, gn0, gn1;
        if (DEC) {
            float a, b;
            unpack2(acc[p][0], a, b); gr0 = a + bir; gr1 = b + bir;
            unpack2(acc[p][1], a, b); gz0 = a + biz; gz1 = b + biz;
            unpack2(acc[p][2], a, b); gn0 = a + bin; gn1 = b + bin;
        } else {
            float2 e;
            e = g_egi[((long)t * 900 + i) * 32 + bp];       gr0 = e.x; gr1 = e.y;
            e = g_egi[((long)t * 900 + 300 + i) * 32 + bp]; gz0 = e.x; gz1 = e.y;
            e = g_egi[((long)t * 900 + 600 + i) * 32 + bp]; gn0 = e.x; gn1 = e.y;
        }
        float hr0, hr1, hz0, hz1, hn0, hn1, a, b;
        unpack2(acc[p][HH0 + 0], a, b); hr0 = a + bhr; hr1 = b + bhr;
        unpack2(acc[p][HH0 + 1], a, b); hz0 = a + bhz; hz1 = b + bhz;
        unpack2(acc[p][HH0 + 2], a, b); hn0 = a + bhn; hn1 = b + bhn;
        float2 hold = hp_cur[i * 32 + bp];
        float r0 = 1.f / (1.f + expf(-(gr0 + hr0)));
        float r1 = 1.f / (1.f + expf(-(gr1 + hr1)));
        float z0 = 1.f / (1.f + expf(-(gz0 + hz0)));
        float z1 = 1.f / (1.f + expf(-(gz1 + hz1)));
        float n0 = tanhf(gn0 + r0 * hn0);
        float n1 = tanhf(gn1 + r1 * hn1);
        float h0 = (1.f - z0) * n0 + z0 * hold.x;
        float h1 = (1.f - z1) * n1 + z1 * hold.y;
        hp_nxt[i * 32 + bp] = make_float2(h0, h1);
    }
}

// ---------------- fused logits GEMM + bias + block argmax ----------------
// grid NBL, threads 256. Block tile 128v x 64b. Thread tile 4v x 4bp.
// Warp: 8 lv (v) x 4 lb (bp) lanes; 4 wv x 2 wb warps.
#define SM_LOGITS (16320 + 62400 + 512)
__global__ void __launch_bounds__(256, 2)
k_logits(const float* __restrict__ outW, const float* __restrict__ outb, int cur) {
    extern __shared__ char sm[];
    float2* h_s = (float2*)sm;               // [KC][34]
    float2* w_s = (float2*)(sm + 16320);     // [KC][130] duplicated
    ull* sm_best = (ull*)(sm + 16320 + 62400);
    const int tid = threadIdx.x;
    const int v0 = blockIdx.x * VT;
    const float2* hp = g_hp[cur];
    if (tid < BSZ) sm_best[tid] = 0ULL;
    const int warp = tid >> 5, lane = tid & 31;
    const int wv = warp & 3, wb = warp >> 2;
    const int lv = lane & 7, lb = lane >> 3;
    const int v0t  = (wv * 8 + lv) * 4;   // 0..124
    const int bp0t = (wb * 4 + lb) * 4;   // 0..28
    ull acc[4][4] = {};
    for (int k0 = 0; k0 < HID; k0 += KC) {
        for (int idx = tid; idx < 32 * KC; idx += 256) {
            int k = idx >> 5, bp = idx & 31;
            h_s[k * 34 + bp] = hp[(k0 + k) * 32 + bp];
        }
        for (int idx = tid; idx < VT * 15; idx += 256) {
            int v = idx / 15, q = idx % 15;
            int vg = v0 + v;
            float4 w = (vg < VOC) ? *(const float4*)&outW[(long)vg * HID + k0 + q * 4]
                                  : make_float4(0, 0, 0, 0);
            w_s[(q * 4 + 0) * 130 + v] = make_float2(w.x, w.x);
            w_s[(q * 4 + 1) * 130 + v] = make_float2(w.y, w.y);
            w_s[(q * 4 + 2) * 130 + v] = make_float2(w.z, w.z);
            w_s[(q * 4 + 3) * 130 + v] = make_float2(w.w, w.w);
        }
        __syncthreads();
#pragma unroll 4
        for (int k = 0; k < KC; k++) {
            ulonglong2 hA = *(const ulonglong2*)&h_s[k * 34 + bp0t];
            ulonglong2 hB = *(const ulonglong2*)&h_s[k * 34 + bp0t + 2];
            ulonglong2 wA = *(const ulonglong2*)&w_s[k * 130 + v0t];
            ulonglong2 wB = *(const ulonglong2*)&w_s[k * 130 + v0t + 2];
            ull hh[4] = {hA.x, hA.y, hB.x, hB.y};
            ull ww[4] = {wA.x, wA.y, wB.x, wB.y};
#pragma unroll
            for (int p = 0; p < 4; p++)
#pragma unroll
                for (int j = 0; j < 4; j++)
                    acc[p][j] = ffma2(hh[p], ww[j], acc[p][j]);
        }
        __syncthreads();
    }
    // epilogue: bias + local argmax keys
    ull best[8] = {};
#pragma unroll
    for (int j = 0; j < 4; j++) {
        int v = v0 + v0t + j;
        if (v >= VOC) continue;
        float bb = outb[v];
        unsigned lowb = 0xFFFFFFFFu - (unsigned)v;
#pragma unroll
        for (int p = 0; p < 4; p++) {
            float a, b; unpack2(acc[p][j], a, b);
            a += bb; b += bb;
            ull ka = ((ull)ordf(a) << 32) | lowb;
            ull kb = ((ull)ordf(b) << 32) | lowb;
            if (ka > best[2 * p])     best[2 * p]     = ka;
            if (kb > best[2 * p + 1]) best[2 * p + 1] = kb;
        }
    }
#pragma unroll
    for (int q = 0; q < 8; q++) atomicMax(&sm_best[bp0t * 2 + q], best[q]);
    __syncthreads();
    if (tid < BSZ) g_part[(long)tid * NBL + blockIdx.x] = sm_best[tid];
}

// ---------------- final per-b argmax over block partials ----------------
__global__ void k_argmax(float* __restrict__ out, int step) {
    __shared__ ull red[8];
    const int b = blockIdx.x, tid = threadIdx.x;
    ull best = 0;
    for (int i = tid; i < NBL; i += 256) {
        ull k = g_part[(long)b * NBL + i];
        if (k > best) best = k;
    }
#pragma unroll
    for (int off = 16; off; off >>= 1) {
        ull o = __shfl_down_sync(0xFFFFFFFFu, best, off);
        if (o > best) best = o;
    }
    if ((tid & 31) == 0) red[tid >> 5] = best;
    __syncthreads();
    if (tid == 0) {
#pragma unroll
        for (int w = 1; w < 8; w++) if (red[w] > best) best = red[w];
        int v = (int)(0xFFFFFFFFu - (unsigned)(best & 0xFFFFFFFFu));
        g_ids[b] = v;
        out[step * BSZ + b] = (float)v;
    }
}

// ---------------- launch ----------------
extern "C" void kernel_launch(void* const* d_in, const int* in_sizes, int n_in,
                              void* d_out, int out_size) {
    const int*   input = (const int*)d_in[0];
    const float* emb   = (const float*)d_in[1];
    const float* eWih  = (const float*)d_in[2];
    const float* eWhh  = (const float*)d_in[3];
    const float* ebih  = (const float*)d_in[4];
    const float* ebhh  = (const float*)d_in[5];
    const float* dWih  = (const float*)d_in[6];
    const float* dWhh  = (const float*)d_in[7];
    const float* dbih  = (const float*)d_in[8];
    const float* dbhh  = (const float*)d_in[9];
    const float* outW  = (const float*)d_in[10];
    const float* outb  = (const float*)d_in[11];
    float* out = (float*)d_out;

    cudaFuncSetAttribute(k_encpre,  cudaFuncAttributeMaxDynamicSharedMemorySize, SM_ENCPRE);
    cudaFuncSetAttribute(k_step<0>, cudaFuncAttributeMaxDynamicSharedMemorySize, SM_STEP);
    cudaFuncSetAttribute(k_step<1>, cudaFuncAttributeMaxDynamicSharedMemorySize, SM_STEP);
    cudaFuncSetAttribute(k_logits,  cudaFuncAttributeMaxDynamicSharedMemorySize, SM_LOGITS);

    k_init<<<38, 256>>>();
    k_encpre<<<dim3(15, 64), 256, SM_ENCPRE>>>(input, emb, eWih, ebih);

    int cur = 0;
    for (int t = 0; t < SEQ; t++) {
        k_step<0><<<30, 160, SM_STEP>>>(emb, eWih, eWhh, ebih, ebhh, t, cur);
        cur ^= 1;
    }
    for (int d = 0; d < SEQ; d++) {
        k_step<1><<<30, 160, SM_STEP>>>(emb, dWih, dWhh, dbih, dbhh, 0, cur);
        cur ^= 1;
        k_logits<<<NBL, 256, SM_LOGITS>>>(outW, outb, cur);
        k_argmax<<<64, 256>>>(out, d);
    }
}

// round 3
// speedup vs baseline: 2.7423x; 1.8161x over previous
#include <cuda_runtime.h>

#define BSZ 64
#define HID 300
#define SEQ 64
#define VOC 100000
#define VT  128
#define NBL ((VOC + VT - 1) / VT)   // 782
#define LKC 20                       // logits k-chunk
#define IPB 4                        // i-rows per step block
#define STEP_BLOCKS 75

typedef unsigned long long ull;

// ---------------- scratch (device globals) ----------------
__device__ float2 g_hp[2][HID * 32];            // packed h, double buffered
__device__ float2 g_egi[SEQ * 900 * 32];        // precomputed encoder input gates (+bias)
__device__ int    g_ids[BSZ];
__device__ ull    g_part[BSZ * NBL];

// ---------------- helpers ----------------
__device__ __forceinline__ unsigned ordf(float f) {
    unsigned u = __float_as_uint(f);
    return (u & 0x80000000u) ? ~u : (u | 0x80000000u);
}
__device__ __forceinline__ ull pack2(float lo, float hi) {
    ull r;
    asm("mov.b64 %0, {%1,%2};" : "=l"(r) : "f"(lo), "f"(hi));
    return r;
}
__device__ __forceinline__ void unpack2(ull v, float& lo, float& hi) {
    asm("mov.b64 {%0,%1}, %2;" : "=f"(lo), "=f"(hi) : "l"(v));
}
__device__ __forceinline__ ull ffma2(ull a, ull b, ull c) {
    ull d;
    asm("fma.rn.f32x2 %0, %1, %2, %3;" : "=l"(d) : "l"(a), "l"(b), "l"(c));
    return d;
}

// ---------------- init ----------------
__global__ void k_init() {
    int i = blockIdx.x * blockDim.x + threadIdx.x;
    if (i < HID * 32) g_hp[0][i] = make_float2(0.f, 0.f);
    if (i < BSZ) g_ids[i] = 0;
}

// ---------------- encoder input-gate pre-GEMM (all 64 steps, one launch) -------
#define SM_ENCPRE (16320 + 31680 + 256)
__global__ void k_encpre(const int* __restrict__ input, const float* __restrict__ emb,
                         const float* __restrict__ W, const float* __restrict__ bias) {
    extern __shared__ char sm[];
    float2* x_s = (float2*)sm;               // [60][34]
    float2* w_s = (float2*)(sm + 16320);     // [60][66] duplicated
    int* sid    = (int*)(sm + 16320 + 31680);
    const int tid = threadIdx.x;
    const int t = blockIdx.y, j0 = blockIdx.x * 64;
    if (tid < BSZ) sid[tid] = input[t * BSZ + tid];
    __syncthreads();
    const int tx = tid & 15, ty = tid >> 4;
    ull acc[2][4] = {};
    for (int k0 = 0; k0 < HID; k0 += 60) {
        for (int idx = tid; idx < 32 * 60; idx += 256) {
            int k = idx >> 5, bp = idx & 31;
            float e0 = emb[(long)sid[2 * bp] * HID + k0 + k];
            float e1 = emb[(long)sid[2 * bp + 1] * HID + k0 + k];
            x_s[k * 34 + bp] = make_float2(e0, e1);
        }
        for (int idx = tid; idx < 64 * 15; idx += 256) {
            int j = idx / 15, q = idx % 15;
            int jg = j0 + j;
            float4 w = (jg < 900) ? *(const float4*)&W[(long)jg * HID + k0 + q * 4]
                                  : make_float4(0, 0, 0, 0);
            w_s[(q * 4 + 0) * 66 + j] = make_float2(w.x, w.x);
            w_s[(q * 4 + 1) * 66 + j] = make_float2(w.y, w.y);
            w_s[(q * 4 + 2) * 66 + j] = make_float2(w.z, w.z);
            w_s[(q * 4 + 3) * 66 + j] = make_float2(w.w, w.w);
        }
        __syncthreads();
#pragma unroll 4
        for (int k = 0; k < 60; k++) {
            ull xp0 = *(const ull*)&x_s[k * 34 + ty];
            ull xp1 = *(const ull*)&x_s[k * 34 + ty + 16];
            ulonglong2 wA = *(const ulonglong2*)&w_s[k * 66 + tx * 4];
            ulonglong2 wB = *(const ulonglong2*)&w_s[k * 66 + tx * 4 + 2];
            acc[0][0] = ffma2(xp0, wA.x, acc[0][0]);
            acc[1][0] = ffma2(xp1, wA.x, acc[1][0]);
            acc[0][1] = ffma2(xp0, wA.y, acc[0][1]);
            acc[1][1] = ffma2(xp1, wA.y, acc[1][1]);
            acc[0][2] = ffma2(xp0, wB.x, acc[0][2]);
            acc[1][2] = ffma2(xp1, wB.x, acc[1][2]);
            acc[0][3] = ffma2(xp0, wB.y, acc[0][3]);
            acc[1][3] = ffma2(xp1, wB.y, acc[1][3]);
        }
        __syncthreads();
    }
#pragma unroll
    for (int jj = 0; jj < 4; jj++) {
        int j = j0 + tx * 4 + jj;
        if (j >= 900) continue;
        float bb = bias[j];
#pragma unroll
        for (int p = 0; p < 2; p++) {
            int bp = ty + 16 * p;
            float a, b; unpack2(acc[p][jj], a, b);
            g_egi[((long)t * 900 + j) * 32 + bp] = make_float2(a + bb, b + bb);
        }
    }
}

// ---------------- fused GRU step (gates + combine), high-occupancy version -----
// grid 75 x 256. Block owns IPB=4 i-rows. Stage ALL of h (+x, +weights dup) to smem.
// Warp w: i_loc = w>>1, k-half = w&1; each warp does all G gates over 150 k.
// Smem partial-reduce across k-halves, then warps 0..3 do the GRU combine.
template <int DEC>
__global__ void __launch_bounds__(256) k_step(
    const float* __restrict__ emb,
    const float* __restrict__ Wih, const float* __restrict__ Whh,
    const float* __restrict__ bih, const float* __restrict__ bhh,
    int t, int cur) {
    constexpr int G = DEC ? 6 : 3;
    constexpr int OFF_W = 76800;                       // h: [300][32] float2
    constexpr int OFF_X = OFF_W + IPB * G * 300 * 8;   // w dup: [IPB*G][300] float2
    constexpr int OFF_R = OFF_X + (DEC ? 76800 : 0);   // x: [300][64] float
    constexpr int OFF_S = OFF_R + IPB * 2 * G * 32 * 8;
    extern __shared__ char sm[];
    float2* h_s  = (float2*)sm;
    float2* w_s  = (float2*)(sm + OFF_W);
    float*  x_sf = (float*)(sm + OFF_X);
    ull*    red  = (ull*)(sm + OFF_R);
    int*    sid  = (int*)(sm + OFF_S);

    const int tid = threadIdx.x;
    const int warp = tid >> 5, lane = tid & 31;
    const int i0 = blockIdx.x * IPB;
    const float2* hp_cur = g_hp[cur];
    float2*       hp_nxt = g_hp[cur ^ 1];

    if (DEC && tid < BSZ) sid[tid] = g_ids[tid];
    __syncthreads();

    // ---- stage h (4800 x 16B) ----
    for (int idx = tid; idx < 4800; idx += 256) {
        int k = idx >> 4, u = idx & 15;
        *(ulonglong2*)&h_s[k * 32 + u * 2] = *(const ulonglong2*)&hp_cur[k * 32 + u * 2];
    }
    // ---- stage weights, duplicated (IPB*G rows x 75 float4) ----
    for (int idx = tid; idx < IPB * G * 75; idx += 256) {
        int r = idx / 75, q = idx % 75;
        int il = r / G, g = r % G;
        const float* W = (DEC && g < 3) ? Wih : Whh;
        int row = (g % 3) * HID + i0 + il;
        float4 w = *(const float4*)&W[(long)row * HID + q * 4];
        float2* dst = &w_s[r * 300 + q * 4];
        dst[0] = make_float2(w.x, w.x);
        dst[1] = make_float2(w.y, w.y);
        dst[2] = make_float2(w.z, w.z);
        dst[3] = make_float2(w.w, w.w);
    }
    // ---- stage x = relu(emb[ids]) as [k][64] floats (DEC only) ----
    if (DEC) {
        for (int idx = tid; idx < 64 * 75; idx += 256) {
            int b = idx / 75, q = idx % 75;
            float4 e = *(const float4*)&emb[(long)sid[b] * HID + q * 4];
            x_sf[(q * 4 + 0) * 64 + b] = fmaxf(e.x, 0.f);
            x_sf[(q * 4 + 1) * 64 + b] = fmaxf(e.y, 0.f);
            x_sf[(q * 4 + 2) * 64 + b] = fmaxf(e.z, 0.f);
            x_sf[(q * 4 + 3) * 64 + b] = fmaxf(e.w, 0.f);
        }
    }
    __syncthreads();

    // ---- GEMM: warp (i_loc, kh) ----
    {
        const int il = warp >> 1, kh = warp & 1;
        const int kbeg = kh * 150, kend = kbeg + 150;
        ull acc[G];
#pragma unroll
        for (int g = 0; g < G; g++) acc[g] = 0ULL;
        const float2* wbase = &w_s[il * G * 300];
#pragma unroll 2
        for (int k = kbeg; k < kend; k++) {
            ull hv = *(const ull*)&h_s[k * 32 + lane];
            ull xv = 0;
            if (DEC) xv = *(const ull*)&x_sf[k * 64 + lane * 2];
#pragma unroll
            for (int g = 0; g < G; g++) {
                ull wd = *(const ull*)&wbase[g * 300 + k];
                ull s = (DEC && g < 3) ? xv : hv;
                acc[g] = ffma2(s, wd, acc[g]);
            }
        }
#pragma unroll
        for (int g = 0; g < G; g++)
            red[((il * 2 + kh) * G + g) * 32 + lane] = acc[g];
    }
    __syncthreads();

    // ---- combine (warps 0..3, one i each; lanes = bp) ----
    if (warp < IPB) {
        const int ig = i0 + warp;
        float s[G][2];
#pragma unroll
        for (int g = 0; g < G; g++) {
            float a0, a1, b0, b1;
            unpack2(red[((warp * 2 + 0) * G + g) * 32 + lane], a0, a1);
            unpack2(red[((warp * 2 + 1) * G + g) * 32 + lane], b0, b1);
            s[g][0] = a0 + b0; s[g][1] = a1 + b1;
        }
        float bhr = bhh[ig], bhz = bhh[HID + ig], bhn = bhh[2 * HID + ig];
        float gr[2], gz[2], gn[2], hr[2], hz[2], hn[2];
        if (DEC) {
            float bir = bih[ig], biz = bih[HID + ig], bin = bih[2 * HID + ig];
            gr[0] = s[0][0] + bir; gr[1] = s[0][1] + bir;
            gz[0] = s[1][0] + biz; gz[1] = s[1][1] + biz;
            gn[0] = s[2][0] + bin; gn[1] = s[2][1] + bin;
            hr[0] = s[3][0] + bhr; hr[1] = s[3][1] + bhr;
            hz[0] = s[4][0] + bhz; hz[1] = s[4][1] + bhz;
            hn[0] = s[5][0] + bhn; hn[1] = s[5][1] + bhn;
        } else {
            float2 e;
            e = g_egi[((long)t * 900 + ig) * 32 + lane];       gr[0] = e.x; gr[1] = e.y;
            e = g_egi[((long)t * 900 + 300 + ig) * 32 + lane]; gz[0] = e.x; gz[1] = e.y;
            e = g_egi[((long)t * 900 + 600 + ig) * 32 + lane]; gn[0] = e.x; gn[1] = e.y;
            hr[0] = s[0][0] + bhr; hr[1] = s[0][1] + bhr;
            hz[0] = s[1][0] + bhz; hz[1] = s[1][1] + bhz;
            hn[0] = s[2][0] + bhn; hn[1] = s[2][1] + bhn;
        }
        float2 hold = h_s[ig * 32 + lane];
        float ho[2] = {hold.x, hold.y};
        float hn2[2];
#pragma unroll
        for (int p = 0; p < 2; p++) {
            float r = 1.f / (1.f + expf(-(gr[p] + hr[p])));
            float z = 1.f / (1.f + expf(-(gz[p] + hz[p])));
            float n = tanhf(gn[p] + r * hn[p]);
            hn2[p] = (1.f - z) * n + z * ho[p];
        }
        hp_nxt[ig * 32 + lane] = make_float2(hn2[0], hn2[1]);
    }
}
#define SM_STEP_ENC (76800 + IPB * 3 * 300 * 8 + IPB * 2 * 3 * 32 * 8 + 256)
#define SM_STEP_DEC (76800 + IPB * 6 * 300 * 8 + 76800 + IPB * 2 * 6 * 32 * 8 + 256)

// ---------------- fused logits GEMM + bias + block argmax ----------------
// grid 782 x 256. Tile 128v x 64b, chunks of LKC=20 k, double-buffered smem with
// register prefetch of next chunk overlapping compute. Thread tile 4v x 4bp (f32x2).
#define SM_LOGITS (21120 + 10880 + 512)
__global__ void __launch_bounds__(256, 3)
k_logits(const float* __restrict__ outW, const float* __restrict__ outb, int cur) {
    extern __shared__ char sm[];
    float*  w_s = (float*)sm;                 // [2][20][132]
    float2* h_s = (float2*)(sm + 21120);      // [2][20][34]
    ull* sm_best = (ull*)(sm + 32000);
    const int tid = threadIdx.x;
    const int v0 = blockIdx.x * VT;
    const float2* hp = g_hp[cur];
    if (tid < BSZ) sm_best[tid] = 0ULL;
    const int warp = tid >> 5, lane = tid & 31;
    const int wv = warp & 3, wb2 = warp >> 2;
    const int lv = lane & 7, lb = lane >> 3;
    const int v0t  = (wv * 8 + lv) * 4;
    const int bp0t = (wb2 * 4 + lb) * 4;

    float4 wr[3];
    ulonglong2 hr[2];
    const int e0 = tid, e1 = tid + 256, e2 = tid + 512;
    const int r0 = e0 / 5, q0 = e0 % 5;
    const int r1 = e1 / 5, q1 = e1 % 5;
    const int r2 = e2 / 5, q2 = e2 % 5;

#define LOADC(c) do {                                                          \
        long kk = (long)(c) * LKC;                                             \
        wr[0] = make_float4(0, 0, 0, 0);                                       \
        wr[1] = make_float4(0, 0, 0, 0);                                       \
        wr[2] = make_float4(0, 0, 0, 0);                                       \
        if (v0 + r0 < VOC) wr[0] = *(const float4*)&outW[(long)(v0 + r0) * HID + kk + q0 * 4]; \
        if (v0 + r1 < VOC) wr[1] = *(const float4*)&outW[(long)(v0 + r1) * HID + kk + q1 * 4]; \
        if (e2 < 640 && v0 + r2 < VOC)                                         \
            wr[2] = *(const float4*)&outW[(long)(v0 + r2) * HID + kk + q2 * 4]; \
        hr[0] = *(const ulonglong2*)&hp[(kk + (e0 >> 4)) * 32 + (e0 & 15) * 2]; \
        if (e1 < 320)                                                          \
            hr[1] = *(const ulonglong2*)&hp[(kk + (e1 >> 4)) * 32 + (e1 & 15) * 2]; \
    } while (0)

#define STOREC(buf) do {                                                       \
        float* wd_ = &w_s[(buf) * 2640];                                       \
        { float* d = &wd_[(q0 * 4) * 132 + r0];                                \
          d[0] = wr[0].x; d[132] = wr[0].y; d[264] = wr[0].z; d[396] = wr[0].w; } \
        { float* d = &wd_[(q1 * 4) * 132 + r1];                                \
          d[0] = wr[1].x; d[132] = wr[1].y; d[264] = wr[1].z; d[396] = wr[1].w; } \
        if (e2 < 640) {                                                        \
          float* d = &wd_[(q2 * 4) * 132 + r2];                                \
          d[0] = wr[2].x; d[132] = wr[2].y; d[264] = wr[2].z; d[396] = wr[2].w; } \
        *(ulonglong2*)&h_s[(buf) * 680 + (e0 >> 4) * 34 + (e0 & 15) * 2] = hr[0]; \
        if (e1 < 320)                                                          \
            *(ulonglong2*)&h_s[(buf) * 680 + (e1 >> 4) * 34 + (e1 & 15) * 2] = hr[1]; \
    } while (0)

    ull acc[4][4] = {};
    LOADC(0);
    for (int c = 0; c < 15; c++) {
        const int buf = c & 1;
        STOREC(buf);
        __syncthreads();
        if (c < 14) LOADC(c + 1);
        const float*  wbp = &w_s[buf * 2640];
        const float2* hbp = &h_s[buf * 680];
#pragma unroll 4
        for (int k = 0; k < LKC; k++) {
            float4 w4 = *(const float4*)&wbp[k * 132 + v0t];
            ulonglong2 hA = *(const ulonglong2*)&hbp[k * 34 + bp0t];
            ulonglong2 hB = *(const ulonglong2*)&hbp[k * 34 + bp0t + 2];
            ull hh[4] = {hA.x, hA.y, hB.x, hB.y};
            ull w0 = pack2(w4.x, w4.x), w1 = pack2(w4.y, w4.y);
            ull w2 = pack2(w4.z, w4.z), w3 = pack2(w4.w, w4.w);
#pragma unroll
            for (int p = 0; p < 4; p++) {
                acc[p][0] = ffma2(hh[p], w0, acc[p][0]);
                acc[p][1] = ffma2(hh[p], w1, acc[p][1]);
                acc[p][2] = ffma2(hh[p], w2, acc[p][2]);
                acc[p][3] = ffma2(hh[p], w3, acc[p][3]);
            }
        }
        __syncthreads();
    }

    // epilogue: bias + argmax keys
    ull best[8] = {};
#pragma unroll
    for (int j = 0; j < 4; j++) {
        int v = v0 + v0t + j;
        if (v >= VOC) continue;
        float bb = outb[v];
        unsigned lowb = 0xFFFFFFFFu - (unsigned)v;
#pragma unroll
        for (int p = 0; p < 4; p++) {
            float a, b; unpack2(acc[p][j], a, b);
            a += bb; b += bb;
            ull ka = ((ull)ordf(a) << 32) | lowb;
            ull kb = ((ull)ordf(b) << 32) | lowb;
            if (ka > best[2 * p])     best[2 * p]     = ka;
            if (kb > best[2 * p + 1]) best[2 * p + 1] = kb;
        }
    }
#pragma unroll
    for (int q = 0; q < 8; q++) atomicMax(&sm_best[bp0t * 2 + q], best[q]);
    __syncthreads();
    if (tid < BSZ) g_part[(long)tid * NBL + blockIdx.x] = sm_best[tid];
#undef LOADC
#undef STOREC
}

// ---------------- final per-b argmax over block partials ----------------
__global__ void k_argmax(float* __restrict__ out, int step) {
    __shared__ ull red[8];
    const int b = blockIdx.x, tid = threadIdx.x;
    ull best = 0;
    for (int i = tid; i < NBL; i += 256) {
        ull k = g_part[(long)b * NBL + i];
        if (k > best) best = k;
    }
#pragma unroll
    for (int off = 16; off; off >>= 1) {
        ull o = __shfl_down_sync(0xFFFFFFFFu, best, off);
        if (o > best) best = o;
    }
    if ((tid & 31) == 0) red[tid >> 5] = best;
    __syncthreads();
    if (tid == 0) {
#pragma unroll
        for (int w = 1; w < 8; w++) if (red[w] > best) best = red[w];
        int v = (int)(0xFFFFFFFFu - (unsigned)(best & 0xFFFFFFFFu));
        g_ids[b] = v;
        out[step * BSZ + b] = (float)v;
    }
}

// ---------------- launch ----------------
extern "C" void kernel_launch(void* const* d_in, const int* in_sizes, int n_in,
                              void* d_out, int out_size) {
    const int*   input = (const int*)d_in[0];
    const float* emb   = (const float*)d_in[1];
    const float* eWih  = (const float*)d_in[2];
    const float* eWhh  = (const float*)d_in[3];
    const float* ebih  = (const float*)d_in[4];
    const float* ebhh  = (const float*)d_in[5];
    const float* dWih  = (const float*)d_in[6];
    const float* dWhh  = (const float*)d_in[7];
    const float* dbih  = (const float*)d_in[8];
    const float* dbhh  = (const float*)d_in[9];
    const float* outW  = (const float*)d_in[10];
    const float* outb  = (const float*)d_in[11];
    float* out = (float*)d_out;

    cudaFuncSetAttribute(k_encpre,  cudaFuncAttributeMaxDynamicSharedMemorySize, SM_ENCPRE);
    cudaFuncSetAttribute(k_step<0>, cudaFuncAttributeMaxDynamicSharedMemorySize, SM_STEP_ENC);
    cudaFuncSetAttribute(k_step<1>, cudaFuncAttributeMaxDynamicSharedMemorySize, SM_STEP_DEC);
    cudaFuncSetAttribute(k_logits,  cudaFuncAttributeMaxDynamicSharedMemorySize, SM_LOGITS);

    k_init<<<38, 256>>>();
    k_encpre<<<dim3(15, 64), 256, SM_ENCPRE>>>(input, emb, eWih, ebih);

    int cur = 0;
    for (int t = 0; t < SEQ; t++) {
        k_step<0><<<STEP_BLOCKS, 256, SM_STEP_ENC>>>(emb, eWih, eWhh, ebih, ebhh, t, cur);
        cur ^= 1;
    }
    for (int d = 0; d < SEQ; d++) {
        k_step<1><<<STEP_BLOCKS, 256, SM_STEP_DEC>>>(emb, dWih, dWhh, dbih, dbhh, 0, cur);
        cur ^= 1;
        k_logits<<<NBL, 256, SM_LOGITS>>>(outW, outb, cur);
        k_argmax<<<64, 256>>>(out, d);
    }
}